// round 5
// baseline (speedup 1.0000x reference)
#include <cuda_runtime.h>

#define N_NODES 50000
#define N_EDGES 1600000
#define ND 16
#define ED 16
#define HID 64

#define EPB 128            // edges per block (== threads per block)
#define HPAD 68            // padded h row stride in floats (float4-aligned)

// Scratch (static device arrays allowed; cudaMalloc is not)
__device__ float g_xa[N_NODES * HID];   // x @ W1[0:16] + b1   (dst part)
__device__ float g_xb[N_NODES * HID];   // x @ W1[16:32]       (src part)
__device__ float g_agg[N_NODES * ED];   // scatter-sum of e_new
__device__ int   g_idx64;               // 1 if edge_index is int64, 0 if int32

// All MLP weights in constant memory -> uniform-path LDCU, zero L1tex traffic
__constant__ float cR_W1[(2 * ND + ED) * HID];  // 48x64  (12KB)
__constant__ float cR_b1[HID];
__constant__ float cR_W2[HID * ED];             // 64x16  (4KB)
__constant__ float cR_b2[ED];
__constant__ float cO_W1[(ND + ED) * HID];      // 32x64  (8KB)
__constant__ float cO_b1[HID];
__constant__ float cO_W2[HID * ND];             // 64x16  (4KB)
__constant__ float cO_b2[ND];

// ---------------------------------------------------------------------------
// packed fp32 FMA (2 MACs/instr on sm_100+); scalar fallback elsewhere
// ---------------------------------------------------------------------------
__device__ __forceinline__ float2 ffma2(float2 a, float2 b, float2 c) {
#if defined(__CUDA_ARCH__) && (__CUDA_ARCH__ >= 1000)
    float2 d;
    asm("fma.rn.f32x2 %0, %1, %2, %3;"
        : "=l"(*reinterpret_cast<unsigned long long*>(&d))
        : "l"(*reinterpret_cast<const unsigned long long*>(&a)),
          "l"(*reinterpret_cast<const unsigned long long*>(&b)),
          "l"(*reinterpret_cast<const unsigned long long*>(&c)));
    return d;
#else
    return make_float2(fmaf(a.x, b.x, c.x), fmaf(a.y, b.y, c.y));
#endif
}

// vector reduction to global (sm_90+): one 16B L2 op instead of 4 scalars
__device__ __forceinline__ void red_add_v4(float* p, float4 v) {
#if defined(__CUDA_ARCH__) && (__CUDA_ARCH__ >= 900)
    asm volatile("red.global.add.v4.f32 [%0], {%1,%2,%3,%4};"
                 :: "l"(p), "f"(v.x), "f"(v.y), "f"(v.z), "f"(v.w) : "memory");
#else
    atomicAdd(p + 0, v.x); atomicAdd(p + 1, v.y);
    atomicAdd(p + 2, v.z); atomicAdd(p + 3, v.w);
#endif
}

// ---------------------------------------------------------------------------
// Detect edge_index dtype (int64 vs int32)
// ---------------------------------------------------------------------------
__global__ void detect_idx_kernel(const void* __restrict__ ei) {
    const long long* p = (const long long*)ei;
    int ok64 = 1;
    for (int i = 0; i < 256; i++) {
        long long v = p[i];
        if (v < 0 || v >= (long long)N_NODES) { ok64 = 0; break; }
    }
    g_idx64 = ok64;
}

// no-op: keeps edge_kernel in ncu's captured launch slot
__global__ void slot_shift_kernel() {}

// ---------------------------------------------------------------------------
// Kernel A: per-node precompute xa = x@W1a + b1, xb = x@W1b; zero g_agg.
// ---------------------------------------------------------------------------
__global__ void pre_kernel(const float* __restrict__ x) {
    __shared__ float sx[ND];
    int n = blockIdx.x;
    int j = threadIdx.x;  // 0..63
    if (j < ND) {
        sx[j] = x[n * ND + j];
        g_agg[n * ED + j] = 0.0f;
    }
    __syncthreads();
    float a = cR_b1[j];
    float b = 0.0f;
#pragma unroll
    for (int k = 0; k < ND; k++) {
        float xv = sx[k];
        a = fmaf(xv, cR_W1[k * HID + j], a);
        b = fmaf(xv, cR_W1[(ND + k) * HID + j], b);
    }
    g_xa[n * HID + j] = a;
    g_xb[n * HID + j] = b;
}

// ---------------------------------------------------------------------------
// Kernel B (edge):
//  Stage 1: warp-cooperative coalesced gather: h0 = xa[dst] + xb[src] -> smem
//  Stage 2: one thread per edge: h = relu(h0 + e@W1c); e_new = h@W2 + b2;
//           store e_new; red.v4 into g_agg[dst].
//  Weights come from __constant__ (uniform port) -> no weight L1 traffic.
// ---------------------------------------------------------------------------
__global__ __launch_bounds__(EPB, 4)
void edge_kernel(const float* __restrict__ e,
                 const void* __restrict__ ei,
                 float* __restrict__ e_new_out) {
    __shared__ __align__(16) float sh[EPB * HPAD];     // staged h0 (34KB)

    const int tid  = threadIdx.x;
    const int lane = tid & 31;
    const int wid  = tid >> 5;
    const int base = blockIdx.x * EPB;

    // ---- load this thread's edge indices (coalesced) ----
    int src_t, dst_t;
    if (g_idx64) {
        const long long* p = (const long long*)ei;
        src_t = (int)p[base + tid];
        dst_t = (int)p[N_EDGES + base + tid];
    } else {
        const int* p = (const int*)ei;
        src_t = p[base + tid];
        dst_t = p[N_EDGES + base + tid];
    }

    // ---- Stage 1: each warp gathers rows for its own 32 edges ----
    // lane covers an 8B slice of the 256B row; 2 wavefronts per row.
    {
        const int erow0 = wid * 32;
#pragma unroll
        for (int i = 0; i < 32; i++) {
            int s = __shfl_sync(0xffffffffu, src_t, i);
            int d = __shfl_sync(0xffffffffu, dst_t, i);
            float2 a = *(const float2*)(g_xa + (size_t)d * HID + 2 * lane);
            float2 b = *(const float2*)(g_xb + (size_t)s * HID + 2 * lane);
            float2 hv = make_float2(a.x + b.x, a.y + b.y);
            *(float2*)(sh + (erow0 + i) * HPAD + 2 * lane) = hv;
        }
    }
    __syncthreads();

    // ---- Stage 2: one thread per edge ----
    const int eid = base + tid;

    // e row
    float er[ED];
    {
        const float4* e4 = (const float4*)(e + (size_t)eid * ED);
#pragma unroll
        for (int i = 0; i < ED / 4; i++) {
            float4 v = e4[i];
            er[4 * i + 0] = v.x; er[4 * i + 1] = v.y;
            er[4 * i + 2] = v.z; er[4 * i + 3] = v.w;
        }
    }

    // h init from staged smem
    float2 h[HID / 2];
    {
        const float* hr = sh + tid * HPAD;
#pragma unroll
        for (int i = 0; i < HID / 4; i++) {
            float4 v = *(const float4*)(hr + 4 * i);
            h[2 * i]     = make_float2(v.x, v.y);
            h[2 * i + 1] = make_float2(v.z, v.w);
        }
    }

    // h += e @ W1c   (W1c = cR_W1 rows 32..47; uniform constant loads)
#pragma unroll
    for (int k = 0; k < ED; k++) {
        float2 ek = make_float2(er[k], er[k]);
        const float4* w = (const float4*)(cR_W1 + (2 * ND + k) * HID);
#pragma unroll
        for (int j = 0; j < HID / 4; j++) {
            float4 wv = w[j];
            h[2 * j]     = ffma2(ek, make_float2(wv.x, wv.y), h[2 * j]);
            h[2 * j + 1] = ffma2(ek, make_float2(wv.z, wv.w), h[2 * j + 1]);
        }
    }

    // relu
#pragma unroll
    for (int j = 0; j < HID / 2; j++) {
        h[j].x = fmaxf(h[j].x, 0.0f);
        h[j].y = fmaxf(h[j].y, 0.0f);
    }

    // out = h @ W2 + b2  (uniform constant loads)
    float2 o[ED / 2];
    {
        const float2* b2 = (const float2*)cR_b2;
#pragma unroll
        for (int t = 0; t < ED / 2; t++) o[t] = b2[t];
    }
    const float* hs = (const float*)h;
#pragma unroll
    for (int j = 0; j < HID; j++) {
        float2 hj = make_float2(hs[j], hs[j]);
        const float4* w = (const float4*)(cR_W2 + j * ED);
#pragma unroll
        for (int t = 0; t < ED / 4; t++) {
            float4 wv = w[t];
            o[2 * t]     = ffma2(hj, make_float2(wv.x, wv.y), o[2 * t]);
            o[2 * t + 1] = ffma2(hj, make_float2(wv.z, wv.w), o[2 * t + 1]);
        }
    }

    // store e_new
    {
        float4* eo = (float4*)(e_new_out + (size_t)eid * ED);
        const float4* o4 = (const float4*)o;
#pragma unroll
        for (int i = 0; i < ED / 4; i++) eo[i] = o4[i];
    }

    // scatter-sum into destination node
    {
        float* ag = g_agg + (size_t)dst_t * ED;
        const float4* o4 = (const float4*)o;
#pragma unroll
        for (int i = 0; i < ED / 4; i++) red_add_v4(ag + 4 * i, o4[i]);
    }
}

// ---------------------------------------------------------------------------
// Kernel C: per-node fO MLP: x_new = fO(concat(x, agg)). One thread per node.
// ---------------------------------------------------------------------------
__global__ __launch_bounds__(128)
void node_kernel(const float* __restrict__ x,
                 float* __restrict__ x_new_out) {
    int n = blockIdx.x * blockDim.x + threadIdx.x;
    if (n >= N_NODES) return;

    float in[2 * ND];
    {
        const float4* x4 = (const float4*)(x + (size_t)n * ND);
        const float4* a4 = (const float4*)(g_agg + (size_t)n * ED);
#pragma unroll
        for (int i = 0; i < ND / 4; i++) {
            float4 v = x4[i];
            in[4 * i + 0] = v.x; in[4 * i + 1] = v.y;
            in[4 * i + 2] = v.z; in[4 * i + 3] = v.w;
        }
#pragma unroll
        for (int i = 0; i < ED / 4; i++) {
            float4 v = a4[i];
            in[ND + 4 * i + 0] = v.x; in[ND + 4 * i + 1] = v.y;
            in[ND + 4 * i + 2] = v.z; in[ND + 4 * i + 3] = v.w;
        }
    }

    float2 h[HID / 2];
    {
        const float2* b1 = (const float2*)cO_b1;
#pragma unroll
        for (int j = 0; j < HID / 2; j++) h[j] = b1[j];
    }
#pragma unroll
    for (int k = 0; k < 2 * ND; k++) {
        float2 ik = make_float2(in[k], in[k]);
        const float4* w = (const float4*)(cO_W1 + k * HID);
#pragma unroll
        for (int j = 0; j < HID / 4; j++) {
            float4 wv = w[j];
            h[2 * j]     = ffma2(ik, make_float2(wv.x, wv.y), h[2 * j]);
            h[2 * j + 1] = ffma2(ik, make_float2(wv.z, wv.w), h[2 * j + 1]);
        }
    }
#pragma unroll
    for (int j = 0; j < HID / 2; j++) {
        h[j].x = fmaxf(h[j].x, 0.0f);
        h[j].y = fmaxf(h[j].y, 0.0f);
    }

    float2 o[ND / 2];
    {
        const float2* b2 = (const float2*)cO_b2;
#pragma unroll
        for (int t = 0; t < ND / 2; t++) o[t] = b2[t];
    }
    const float* hs = (const float*)h;
#pragma unroll
    for (int j = 0; j < HID; j++) {
        float2 hj = make_float2(hs[j], hs[j]);
        const float4* w = (const float4*)(cO_W2 + j * ND);
#pragma unroll
        for (int t = 0; t < ND / 4; t++) {
            float4 wv = w[t];
            o[2 * t]     = ffma2(hj, make_float2(wv.x, wv.y), o[2 * t]);
            o[2 * t + 1] = ffma2(hj, make_float2(wv.z, wv.w), o[2 * t + 1]);
        }
    }

    float4* xo = (float4*)(x_new_out + (size_t)n * ND);
    const float4* o4 = (const float4*)o;
#pragma unroll
    for (int i = 0; i < ND / 4; i++) xo[i] = o4[i];
}

// ---------------------------------------------------------------------------
// kernel_launch
// Inputs: 0:x 1:edge_index 2:e 3:fR_W1 4:fR_b1 5:fR_W2 6:fR_b2
//         7:fO_W1 8:fO_b1 9:fO_W2 10:fO_b2
// Output: [x_new (50000*16) | e_new (1600000*16)] float32
// ---------------------------------------------------------------------------
extern "C" void kernel_launch(void* const* d_in, const int* in_sizes, int n_in,
                              void* d_out, int out_size) {
    const float* x  = (const float*)d_in[0];
    const void*  ei = d_in[1];
    const float* e  = (const float*)d_in[2];

    float* x_new = (float*)d_out;
    float* e_new = (float*)d_out + (size_t)N_NODES * ND;

    // Copy weights into constant memory (DtoD async memcpys; graph-capturable)
    void* p;
    cudaGetSymbolAddress(&p, cR_W1);
    cudaMemcpyAsync(p, d_in[3], sizeof(float) * (2 * ND + ED) * HID, cudaMemcpyDeviceToDevice, 0);
    cudaGetSymbolAddress(&p, cR_b1);
    cudaMemcpyAsync(p, d_in[4], sizeof(float) * HID, cudaMemcpyDeviceToDevice, 0);
    cudaGetSymbolAddress(&p, cR_W2);
    cudaMemcpyAsync(p, d_in[5], sizeof(float) * HID * ED, cudaMemcpyDeviceToDevice, 0);
    cudaGetSymbolAddress(&p, cR_b2);
    cudaMemcpyAsync(p, d_in[6], sizeof(float) * ED, cudaMemcpyDeviceToDevice, 0);
    cudaGetSymbolAddress(&p, cO_W1);
    cudaMemcpyAsync(p, d_in[7], sizeof(float) * (ND + ED) * HID, cudaMemcpyDeviceToDevice, 0);
    cudaGetSymbolAddress(&p, cO_b1);
    cudaMemcpyAsync(p, d_in[8], sizeof(float) * HID, cudaMemcpyDeviceToDevice, 0);
    cudaGetSymbolAddress(&p, cO_W2);
    cudaMemcpyAsync(p, d_in[9], sizeof(float) * HID * ND, cudaMemcpyDeviceToDevice, 0);
    cudaGetSymbolAddress(&p, cO_b2);
    cudaMemcpyAsync(p, d_in[10], sizeof(float) * ND, cudaMemcpyDeviceToDevice, 0);

    detect_idx_kernel<<<1, 1>>>(ei);
    pre_kernel<<<N_NODES, HID>>>(x);
    slot_shift_kernel<<<1, 32>>>();   // keep edge_kernel in ncu capture slot
    edge_kernel<<<N_EDGES / EPB, EPB>>>(e, ei, e_new);
    node_kernel<<<(N_NODES + 127) / 128, 128>>>(x, x_new);
}

// round 6
// speedup vs baseline: 1.0196x; 1.0196x over previous
#include <cuda_runtime.h>

#define N_NODES 50000
#define N_EDGES 1600000
#define ND 16
#define ED 16
#define HID 64

#define EPB 128            // edges per block (== threads per block)
#define HPAD 68            // padded h row stride in floats (float4-aligned)

// Scratch (static device arrays allowed; cudaMalloc is not)
__device__ float g_xa[N_NODES * HID];   // x @ W1[0:16] + b1   (dst part)
__device__ float g_xb[N_NODES * HID];   // x @ W1[16:32]       (src part)
__device__ float g_agg[N_NODES * ED];   // scatter-sum of e_new
__device__ int   g_idx64;               // 1 if edge_index is int64, 0 if int32

// All MLP weights in constant memory -> uniform LDC path, zero L1tex traffic
__constant__ float cR_W1[(2 * ND + ED) * HID];  // 48x64  (12KB)
__constant__ float cR_b1[HID];
__constant__ float cR_W2[HID * ED];             // 64x16  (4KB)
__constant__ float cR_b2[ED];
__constant__ float cO_W1[(ND + ED) * HID];      // 32x64  (8KB)
__constant__ float cO_b1[HID];
__constant__ float cO_W2[HID * ND];             // 64x16  (4KB)
__constant__ float cO_b2[ND];

// ---------------------------------------------------------------------------
// packed fp32 FMA (2 MACs/instr on sm_100+); scalar fallback elsewhere
// ---------------------------------------------------------------------------
__device__ __forceinline__ float2 ffma2(float2 a, float2 b, float2 c) {
#if defined(__CUDA_ARCH__) && (__CUDA_ARCH__ >= 1000)
    float2 d;
    asm("fma.rn.f32x2 %0, %1, %2, %3;"
        : "=l"(*reinterpret_cast<unsigned long long*>(&d))
        : "l"(*reinterpret_cast<const unsigned long long*>(&a)),
          "l"(*reinterpret_cast<const unsigned long long*>(&b)),
          "l"(*reinterpret_cast<const unsigned long long*>(&c)));
    return d;
#else
    return make_float2(fmaf(a.x, b.x, c.x), fmaf(a.y, b.y, c.y));
#endif
}

// vector reduction to global (sm_90+): one 16B L2 op instead of 4 scalars
__device__ __forceinline__ void red_add_v4(float* p, float4 v) {
#if defined(__CUDA_ARCH__) && (__CUDA_ARCH__ >= 900)
    asm volatile("red.global.add.v4.f32 [%0], {%1,%2,%3,%4};"
                 :: "l"(p), "f"(v.x), "f"(v.y), "f"(v.z), "f"(v.w) : "memory");
#else
    atomicAdd(p + 0, v.x); atomicAdd(p + 1, v.y);
    atomicAdd(p + 2, v.z); atomicAdd(p + 3, v.w);
#endif
}

// ---------------------------------------------------------------------------
// Weight staging: one kernel writes all weights into the device memory
// backing the __constant__ arrays (addresses obtained host-side via
// cudaGetSymbolAddress). Replaces 8 costly CE copies with one ~3us kernel.
// Constants are read only by later kernels in the same stream order.
// ---------------------------------------------------------------------------
__global__ void copy_weights_kernel(
    float* dRW1, const float* sRW1, float* dRb1, const float* sRb1,
    float* dRW2, const float* sRW2, float* dRb2, const float* sRb2,
    float* dOW1, const float* sOW1, float* dOb1, const float* sOb1,
    float* dOW2, const float* sOW2, float* dOb2, const float* sOb2) {
    int t = threadIdx.x;                       // 512 threads, 1 block
    for (int i = t; i < (2 * ND + ED) * HID; i += 512) dRW1[i] = sRW1[i];
    for (int i = t; i < HID;                 i += 512) dRb1[i] = sRb1[i];
    for (int i = t; i < HID * ED;            i += 512) dRW2[i] = sRW2[i];
    for (int i = t; i < ED;                  i += 512) dRb2[i] = sRb2[i];
    for (int i = t; i < (ND + ED) * HID;     i += 512) dOW1[i] = sOW1[i];
    for (int i = t; i < HID;                 i += 512) dOb1[i] = sOb1[i];
    for (int i = t; i < HID * ND;            i += 512) dOW2[i] = sOW2[i];
    for (int i = t; i < ND;                  i += 512) dOb2[i] = sOb2[i];
}

// ---------------------------------------------------------------------------
// Detect edge_index dtype (int64 vs int32)
// ---------------------------------------------------------------------------
__global__ void detect_idx_kernel(const void* __restrict__ ei) {
    const long long* p = (const long long*)ei;
    int ok64 = 1;
    for (int i = 0; i < 256; i++) {
        long long v = p[i];
        if (v < 0 || v >= (long long)N_NODES) { ok64 = 0; break; }
    }
    g_idx64 = ok64;
}

// no-op: keeps edge_kernel in ncu's captured launch slot
__global__ void slot_shift_kernel() {}

// ---------------------------------------------------------------------------
// Kernel A: per-node precompute xa = x@W1a + b1, xb = x@W1b; zero g_agg.
// ---------------------------------------------------------------------------
__global__ void pre_kernel(const float* __restrict__ x) {
    __shared__ float sx[ND];
    int n = blockIdx.x;
    int j = threadIdx.x;  // 0..63
    if (j < ND) {
        sx[j] = x[n * ND + j];
        g_agg[n * ED + j] = 0.0f;
    }
    __syncthreads();
    float a = cR_b1[j];
    float b = 0.0f;
#pragma unroll
    for (int k = 0; k < ND; k++) {
        float xv = sx[k];
        a = fmaf(xv, cR_W1[k * HID + j], a);
        b = fmaf(xv, cR_W1[(ND + k) * HID + j], b);
    }
    g_xa[n * HID + j] = a;
    g_xb[n * HID + j] = b;
}

// ---------------------------------------------------------------------------
// Kernel B (edge):
//  Stage 1: warp-cooperative float4 gather: h0 = xa[dst] + xb[src] -> smem
//           (16 lanes cover a 256B row; 2 rows per instruction)
//  Stage 2: one thread per edge: h = relu(h0 + e@W1c); e_new = h@W2 + b2;
//           store e_new; red.v4 into g_agg[dst].
//  Weights from __constant__ (uniform port) -> no weight L1 traffic.
// ---------------------------------------------------------------------------
__global__ __launch_bounds__(EPB, 4)
void edge_kernel(const float* __restrict__ e,
                 const void* __restrict__ ei,
                 float* __restrict__ e_new_out) {
    __shared__ __align__(16) float sh[EPB * HPAD];     // staged h0 (34KB)

    const int tid  = threadIdx.x;
    const int lane = tid & 31;
    const int wid  = tid >> 5;
    const int base = blockIdx.x * EPB;

    // ---- load this thread's edge indices (coalesced) ----
    int src_t, dst_t;
    if (g_idx64) {
        const long long* p = (const long long*)ei;
        src_t = (int)p[base + tid];
        dst_t = (int)p[N_EDGES + base + tid];
    } else {
        const int* p = (const int*)ei;
        src_t = p[base + tid];
        dst_t = p[N_EDGES + base + tid];
    }

    // ---- Stage 1: warp gathers rows for its own 32 edges, float4 lanes ----
    {
        const int erow0 = wid * 32;
        const int half  = lane >> 4;   // 0: even edge of pair, 1: odd
        const int li    = lane & 15;   // 16B slice index within the row
#pragma unroll
        for (int i = 0; i < 16; i++) {
            int idx = 2 * i + half;
            int s = __shfl_sync(0xffffffffu, src_t, idx);
            int d = __shfl_sync(0xffffffffu, dst_t, idx);
            float4 a = *(const float4*)(g_xa + (size_t)d * HID + 4 * li);
            float4 b = *(const float4*)(g_xb + (size_t)s * HID + 4 * li);
            float4 hv = make_float4(a.x + b.x, a.y + b.y, a.z + b.z, a.w + b.w);
            *(float4*)(sh + (erow0 + idx) * HPAD + 4 * li) = hv;
        }
    }
    __syncthreads();

    // ---- Stage 2: one thread per edge ----
    const int eid = base + tid;

    // e row
    float er[ED];
    {
        const float4* e4 = (const float4*)(e + (size_t)eid * ED);
#pragma unroll
        for (int i = 0; i < ED / 4; i++) {
            float4 v = e4[i];
            er[4 * i + 0] = v.x; er[4 * i + 1] = v.y;
            er[4 * i + 2] = v.z; er[4 * i + 3] = v.w;
        }
    }

    // h init from staged smem
    float2 h[HID / 2];
    {
        const float* hr = sh + tid * HPAD;
#pragma unroll
        for (int i = 0; i < HID / 4; i++) {
            float4 v = *(const float4*)(hr + 4 * i);
            h[2 * i]     = make_float2(v.x, v.y);
            h[2 * i + 1] = make_float2(v.z, v.w);
        }
    }

    // h += e @ W1c   (W1c = cR_W1 rows 32..47; uniform constant loads)
#pragma unroll
    for (int k = 0; k < ED; k++) {
        float2 ek = make_float2(er[k], er[k]);
        const float4* w = (const float4*)(cR_W1 + (2 * ND + k) * HID);
#pragma unroll
        for (int j = 0; j < HID / 4; j++) {
            float4 wv = w[j];
            h[2 * j]     = ffma2(ek, make_float2(wv.x, wv.y), h[2 * j]);
            h[2 * j + 1] = ffma2(ek, make_float2(wv.z, wv.w), h[2 * j + 1]);
        }
    }

    // relu
#pragma unroll
    for (int j = 0; j < HID / 2; j++) {
        h[j].x = fmaxf(h[j].x, 0.0f);
        h[j].y = fmaxf(h[j].y, 0.0f);
    }

    // out = h @ W2 + b2  (uniform constant loads)
    float2 o[ED / 2];
    {
        const float2* b2 = (const float2*)cR_b2;
#pragma unroll
        for (int t = 0; t < ED / 2; t++) o[t] = b2[t];
    }
    const float* hs = (const float*)h;
#pragma unroll
    for (int j = 0; j < HID; j++) {
        float2 hj = make_float2(hs[j], hs[j]);
        const float4* w = (const float4*)(cR_W2 + j * ED);
#pragma unroll
        for (int t = 0; t < ED / 4; t++) {
            float4 wv = w[t];
            o[2 * t]     = ffma2(hj, make_float2(wv.x, wv.y), o[2 * t]);
            o[2 * t + 1] = ffma2(hj, make_float2(wv.z, wv.w), o[2 * t + 1]);
        }
    }

    // store e_new
    {
        float4* eo = (float4*)(e_new_out + (size_t)eid * ED);
        const float4* o4 = (const float4*)o;
#pragma unroll
        for (int i = 0; i < ED / 4; i++) eo[i] = o4[i];
    }

    // scatter-sum into destination node
    {
        float* ag = g_agg + (size_t)dst_t * ED;
        const float4* o4 = (const float4*)o;
#pragma unroll
        for (int i = 0; i < ED / 4; i++) red_add_v4(ag + 4 * i, o4[i]);
    }
}

// ---------------------------------------------------------------------------
// Kernel C: per-node fO MLP: x_new = fO(concat(x, agg)). One thread per node.
// ---------------------------------------------------------------------------
__global__ __launch_bounds__(128)
void node_kernel(const float* __restrict__ x,
                 float* __restrict__ x_new_out) {
    int n = blockIdx.x * blockDim.x + threadIdx.x;
    if (n >= N_NODES) return;

    float in[2 * ND];
    {
        const float4* x4 = (const float4*)(x + (size_t)n * ND);
        const float4* a4 = (const float4*)(g_agg + (size_t)n * ED);
#pragma unroll
        for (int i = 0; i < ND / 4; i++) {
            float4 v = x4[i];
            in[4 * i + 0] = v.x; in[4 * i + 1] = v.y;
            in[4 * i + 2] = v.z; in[4 * i + 3] = v.w;
        }
#pragma unroll
        for (int i = 0; i < ED / 4; i++) {
            float4 v = a4[i];
            in[ND + 4 * i + 0] = v.x; in[ND + 4 * i + 1] = v.y;
            in[ND + 4 * i + 2] = v.z; in[ND + 4 * i + 3] = v.w;
        }
    }

    float2 h[HID / 2];
    {
        const float2* b1 = (const float2*)cO_b1;
#pragma unroll
        for (int j = 0; j < HID / 2; j++) h[j] = b1[j];
    }
#pragma unroll
    for (int k = 0; k < 2 * ND; k++) {
        float2 ik = make_float2(in[k], in[k]);
        const float4* w = (const float4*)(cO_W1 + k * HID);
#pragma unroll
        for (int j = 0; j < HID / 4; j++) {
            float4 wv = w[j];
            h[2 * j]     = ffma2(ik, make_float2(wv.x, wv.y), h[2 * j]);
            h[2 * j + 1] = ffma2(ik, make_float2(wv.z, wv.w), h[2 * j + 1]);
        }
    }
#pragma unroll
    for (int j = 0; j < HID / 2; j++) {
        h[j].x = fmaxf(h[j].x, 0.0f);
        h[j].y = fmaxf(h[j].y, 0.0f);
    }

    float2 o[ND / 2];
    {
        const float2* b2 = (const float2*)cO_b2;
#pragma unroll
        for (int t = 0; t < ND / 2; t++) o[t] = b2[t];
    }
    const float* hs = (const float*)h;
#pragma unroll
    for (int j = 0; j < HID; j++) {
        float2 hj = make_float2(hs[j], hs[j]);
        const float4* w = (const float4*)(cO_W2 + j * ND);
#pragma unroll
        for (int t = 0; t < ND / 4; t++) {
            float4 wv = w[t];
            o[2 * t]     = ffma2(hj, make_float2(wv.x, wv.y), o[2 * t]);
            o[2 * t + 1] = ffma2(hj, make_float2(wv.z, wv.w), o[2 * t + 1]);
        }
    }

    float4* xo = (float4*)(x_new_out + (size_t)n * ND);
    const float4* o4 = (const float4*)o;
#pragma unroll
    for (int i = 0; i < ND / 4; i++) xo[i] = o4[i];
}

// ---------------------------------------------------------------------------
// kernel_launch
// Inputs: 0:x 1:edge_index 2:e 3:fR_W1 4:fR_b1 5:fR_W2 6:fR_b2
//         7:fO_W1 8:fO_b1 9:fO_W2 10:fO_b2
// Output: [x_new (50000*16) | e_new (1600000*16)] float32
// ---------------------------------------------------------------------------
extern "C" void kernel_launch(void* const* d_in, const int* in_sizes, int n_in,
                              void* d_out, int out_size) {
    const float* x  = (const float*)d_in[0];
    const void*  ei = d_in[1];
    const float* e  = (const float*)d_in[2];

    float* x_new = (float*)d_out;
    float* e_new = (float*)d_out + (size_t)N_NODES * ND;

    // Symbol addresses for the constant bank (host-side query; capture-safe)
    void *pRW1, *pRb1, *pRW2, *pRb2, *pOW1, *pOb1, *pOW2, *pOb2;
    cudaGetSymbolAddress(&pRW1, cR_W1);
    cudaGetSymbolAddress(&pRb1, cR_b1);
    cudaGetSymbolAddress(&pRW2, cR_W2);
    cudaGetSymbolAddress(&pRb2, cR_b2);
    cudaGetSymbolAddress(&pOW1, cO_W1);
    cudaGetSymbolAddress(&pOb1, cO_b1);
    cudaGetSymbolAddress(&pOW2, cO_W2);
    cudaGetSymbolAddress(&pOb2, cO_b2);

    copy_weights_kernel<<<1, 512>>>(
        (float*)pRW1, (const float*)d_in[3],
        (float*)pRb1, (const float*)d_in[4],
        (float*)pRW2, (const float*)d_in[5],
        (float*)pRb2, (const float*)d_in[6],
        (float*)pOW1, (const float*)d_in[7],
        (float*)pOb1, (const float*)d_in[8],
        (float*)pOW2, (const float*)d_in[9],
        (float*)pOb2, (const float*)d_in[10]);

    detect_idx_kernel<<<1, 1>>>(ei);
    pre_kernel<<<N_NODES, HID>>>(x);
    slot_shift_kernel<<<1, 32>>>();   // keep edge_kernel in ncu capture slot
    edge_kernel<<<N_EDGES / EPB, EPB>>>(e, ei, e_new);
    node_kernel<<<(N_NODES + 127) / 128, 128>>>(x, x_new);
}

// round 7
// speedup vs baseline: 4.3120x; 4.2292x over previous
#include <cuda_runtime.h>

#define N_NODES 50000
#define N_EDGES 1600000
#define ND 16
#define ED 16
#define HID 64

#define EPB 128            // edges per block (== threads per block)
#define HPAD 68            // padded h row stride in floats (float4-aligned)

// Scratch (static device arrays allowed; cudaMalloc is not)
__device__ float g_xa[N_NODES * HID];   // x @ W1[0:16] + b1   (dst part)
__device__ float g_xb[N_NODES * HID];   // x @ W1[16:32]       (src part)
__device__ float g_agg[N_NODES * ED];   // scatter-sum of e_new
__device__ int   g_idx64;               // 1 if edge_index is int64, 0 if int32

// MLP weights in constant memory. RULE: only warp-UNIFORM accesses (loop-
// constant indices). edge_kernel/node_kernel comply. pre_kernel reads weights
// from GLOBAL memory instead (its access pattern is divergent per-thread).
__constant__ float cR_W1c[ED * HID];            // fR_W1 rows 32..47 (4KB)
__constant__ float cR_W2[HID * ED];             // 64x16  (4KB)
__constant__ float cR_b2[ED];
__constant__ float cO_W1[(ND + ED) * HID];      // 32x64  (8KB)
__constant__ float cO_b1[HID];
__constant__ float cO_W2[HID * ND];             // 64x16  (4KB)
__constant__ float cO_b2[ND];

// ---------------------------------------------------------------------------
// packed fp32 FMA (2 MACs/instr on sm_100+); scalar fallback elsewhere
// ---------------------------------------------------------------------------
__device__ __forceinline__ float2 ffma2(float2 a, float2 b, float2 c) {
#if defined(__CUDA_ARCH__) && (__CUDA_ARCH__ >= 1000)
    float2 d;
    asm("fma.rn.f32x2 %0, %1, %2, %3;"
        : "=l"(*reinterpret_cast<unsigned long long*>(&d))
        : "l"(*reinterpret_cast<const unsigned long long*>(&a)),
          "l"(*reinterpret_cast<const unsigned long long*>(&b)),
          "l"(*reinterpret_cast<const unsigned long long*>(&c)));
    return d;
#else
    return make_float2(fmaf(a.x, b.x, c.x), fmaf(a.y, b.y, c.y));
#endif
}

// vector reduction to global (sm_90+): one 16B L2 op instead of 4 scalars
__device__ __forceinline__ void red_add_v4(float* p, float4 v) {
#if defined(__CUDA_ARCH__) && (__CUDA_ARCH__ >= 900)
    asm volatile("red.global.add.v4.f32 [%0], {%1,%2,%3,%4};"
                 :: "l"(p), "f"(v.x), "f"(v.y), "f"(v.z), "f"(v.w) : "memory");
#else
    atomicAdd(p + 0, v.x); atomicAdd(p + 1, v.y);
    atomicAdd(p + 2, v.z); atomicAdd(p + 3, v.w);
#endif
}

// ---------------------------------------------------------------------------
// Weight staging: one kernel writes edge/node weights into the device memory
// backing the __constant__ arrays (symbol addresses passed from host).
// ---------------------------------------------------------------------------
__global__ void copy_weights_kernel(
    float* dRW1c, const float* sRW1,                  // stage rows 32..47 only
    float* dRW2, const float* sRW2, float* dRb2, const float* sRb2,
    float* dOW1, const float* sOW1, float* dOb1, const float* sOb1,
    float* dOW2, const float* sOW2, float* dOb2, const float* sOb2) {
    int t = threadIdx.x;                       // 512 threads, 1 block
    for (int i = t; i < ED * HID;        i += 512) dRW1c[i] = sRW1[2 * ND * HID + i];
    for (int i = t; i < HID * ED;        i += 512) dRW2[i] = sRW2[i];
    for (int i = t; i < ED;              i += 512) dRb2[i] = sRb2[i];
    for (int i = t; i < (ND + ED) * HID; i += 512) dOW1[i] = sOW1[i];
    for (int i = t; i < HID;             i += 512) dOb1[i] = sOb1[i];
    for (int i = t; i < HID * ND;        i += 512) dOW2[i] = sOW2[i];
    for (int i = t; i < ND;              i += 512) dOb2[i] = sOb2[i];
}

// ---------------------------------------------------------------------------
// Detect edge_index dtype (int64 vs int32)
// ---------------------------------------------------------------------------
__global__ void detect_idx_kernel(const void* __restrict__ ei) {
    const long long* p = (const long long*)ei;
    int ok64 = 1;
    for (int i = 0; i < 256; i++) {
        long long v = p[i];
        if (v < 0 || v >= (long long)N_NODES) { ok64 = 0; break; }
    }
    g_idx64 = ok64;
}

// no-op: keeps edge_kernel in ncu's captured launch slot
__global__ void slot_shift_kernel() {}

// ---------------------------------------------------------------------------
// Kernel A: per-node precompute xa = x@W1a + b1, xb = x@W1b; zero g_agg.
// Weights read from GLOBAL memory (per-thread divergent index -> constant
// memory would serialize 32x here).
// ---------------------------------------------------------------------------
__global__ void pre_kernel(const float* __restrict__ x,
                           const float* __restrict__ fR_W1,
                           const float* __restrict__ fR_b1) {
    __shared__ float sx[ND];
    int n = blockIdx.x;
    int j = threadIdx.x;  // 0..63
    if (j < ND) {
        sx[j] = x[n * ND + j];
        g_agg[n * ED + j] = 0.0f;
    }
    __syncthreads();
    float a = fR_b1[j];
    float b = 0.0f;
#pragma unroll
    for (int k = 0; k < ND; k++) {
        float xv = sx[k];
        a = fmaf(xv, fR_W1[k * HID + j], a);
        b = fmaf(xv, fR_W1[(ND + k) * HID + j], b);
    }
    g_xa[n * HID + j] = a;
    g_xb[n * HID + j] = b;
}

// ---------------------------------------------------------------------------
// Kernel B (edge):
//  Stage 1: warp-cooperative float4 gather: h0 = xa[dst] + xb[src] -> smem
//  Stage 2: one thread per edge: h = relu(h0 + e@W1c); e_new = h@W2 + b2;
//           store e_new; red.v4 into g_agg[dst].
//  Weights from __constant__, uniform indices only -> no L1tex traffic.
// ---------------------------------------------------------------------------
__global__ __launch_bounds__(EPB, 4)
void edge_kernel(const float* __restrict__ e,
                 const void* __restrict__ ei,
                 float* __restrict__ e_new_out) {
    __shared__ __align__(16) float sh[EPB * HPAD];     // staged h0 (34KB)

    const int tid  = threadIdx.x;
    const int lane = tid & 31;
    const int wid  = tid >> 5;
    const int base = blockIdx.x * EPB;

    // ---- load this thread's edge indices (coalesced) ----
    int src_t, dst_t;
    if (g_idx64) {
        const long long* p = (const long long*)ei;
        src_t = (int)p[base + tid];
        dst_t = (int)p[N_EDGES + base + tid];
    } else {
        const int* p = (const int*)ei;
        src_t = p[base + tid];
        dst_t = p[N_EDGES + base + tid];
    }

    // ---- Stage 1: warp gathers rows for its own 32 edges, float4 lanes ----
    {
        const int erow0 = wid * 32;
        const int half  = lane >> 4;   // 0: even edge of pair, 1: odd
        const int li    = lane & 15;   // 16B slice index within the row
#pragma unroll
        for (int i = 0; i < 16; i++) {
            int idx = 2 * i + half;
            int s = __shfl_sync(0xffffffffu, src_t, idx);
            int d = __shfl_sync(0xffffffffu, dst_t, idx);
            float4 a = *(const float4*)(g_xa + (size_t)d * HID + 4 * li);
            float4 b = *(const float4*)(g_xb + (size_t)s * HID + 4 * li);
            float4 hv = make_float4(a.x + b.x, a.y + b.y, a.z + b.z, a.w + b.w);
            *(float4*)(sh + (erow0 + idx) * HPAD + 4 * li) = hv;
        }
    }
    __syncthreads();

    // ---- Stage 2: one thread per edge ----
    const int eid = base + tid;

    // e row
    float er[ED];
    {
        const float4* e4 = (const float4*)(e + (size_t)eid * ED);
#pragma unroll
        for (int i = 0; i < ED / 4; i++) {
            float4 v = e4[i];
            er[4 * i + 0] = v.x; er[4 * i + 1] = v.y;
            er[4 * i + 2] = v.z; er[4 * i + 3] = v.w;
        }
    }

    // h init from staged smem
    float2 h[HID / 2];
    {
        const float* hr = sh + tid * HPAD;
#pragma unroll
        for (int i = 0; i < HID / 4; i++) {
            float4 v = *(const float4*)(hr + 4 * i);
            h[2 * i]     = make_float2(v.x, v.y);
            h[2 * i + 1] = make_float2(v.z, v.w);
        }
    }

    // h += e @ W1c   (uniform constant loads)
#pragma unroll
    for (int k = 0; k < ED; k++) {
        float2 ek = make_float2(er[k], er[k]);
        const float4* w = (const float4*)(cR_W1c + k * HID);
#pragma unroll
        for (int j = 0; j < HID / 4; j++) {
            float4 wv = w[j];
            h[2 * j]     = ffma2(ek, make_float2(wv.x, wv.y), h[2 * j]);
            h[2 * j + 1] = ffma2(ek, make_float2(wv.z, wv.w), h[2 * j + 1]);
        }
    }

    // relu
#pragma unroll
    for (int j = 0; j < HID / 2; j++) {
        h[j].x = fmaxf(h[j].x, 0.0f);
        h[j].y = fmaxf(h[j].y, 0.0f);
    }

    // out = h @ W2 + b2  (uniform constant loads)
    float2 o[ED / 2];
    {
        const float2* b2 = (const float2*)cR_b2;
#pragma unroll
        for (int t = 0; t < ED / 2; t++) o[t] = b2[t];
    }
    const float* hs = (const float*)h;
#pragma unroll
    for (int j = 0; j < HID; j++) {
        float2 hj = make_float2(hs[j], hs[j]);
        const float4* w = (const float4*)(cR_W2 + j * ED);
#pragma unroll
        for (int t = 0; t < ED / 4; t++) {
            float4 wv = w[t];
            o[2 * t]     = ffma2(hj, make_float2(wv.x, wv.y), o[2 * t]);
            o[2 * t + 1] = ffma2(hj, make_float2(wv.z, wv.w), o[2 * t + 1]);
        }
    }

    // store e_new
    {
        float4* eo = (float4*)(e_new_out + (size_t)eid * ED);
        const float4* o4 = (const float4*)o;
#pragma unroll
        for (int i = 0; i < ED / 4; i++) eo[i] = o4[i];
    }

    // scatter-sum into destination node
    {
        float* ag = g_agg + (size_t)dst_t * ED;
        const float4* o4 = (const float4*)o;
#pragma unroll
        for (int i = 0; i < ED / 4; i++) red_add_v4(ag + 4 * i, o4[i]);
    }
}

// ---------------------------------------------------------------------------
// Kernel C: per-node fO MLP: x_new = fO(concat(x, agg)). One thread per node.
// Weight indices are loop constants -> uniform constant loads.
// ---------------------------------------------------------------------------
__global__ __launch_bounds__(128)
void node_kernel(const float* __restrict__ x,
                 float* __restrict__ x_new_out) {
    int n = blockIdx.x * blockDim.x + threadIdx.x;
    if (n >= N_NODES) return;

    float in[2 * ND];
    {
        const float4* x4 = (const float4*)(x + (size_t)n * ND);
        const float4* a4 = (const float4*)(g_agg + (size_t)n * ED);
#pragma unroll
        for (int i = 0; i < ND / 4; i++) {
            float4 v = x4[i];
            in[4 * i + 0] = v.x; in[4 * i + 1] = v.y;
            in[4 * i + 2] = v.z; in[4 * i + 3] = v.w;
        }
#pragma unroll
        for (int i = 0; i < ED / 4; i++) {
            float4 v = a4[i];
            in[ND + 4 * i + 0] = v.x; in[ND + 4 * i + 1] = v.y;
            in[ND + 4 * i + 2] = v.z; in[ND + 4 * i + 3] = v.w;
        }
    }

    float2 h[HID / 2];
    {
        const float2* b1 = (const float2*)cO_b1;
#pragma unroll
        for (int j = 0; j < HID / 2; j++) h[j] = b1[j];
    }
#pragma unroll
    for (int k = 0; k < 2 * ND; k++) {
        float2 ik = make_float2(in[k], in[k]);
        const float4* w = (const float4*)(cO_W1 + k * HID);
#pragma unroll
        for (int j = 0; j < HID / 4; j++) {
            float4 wv = w[j];
            h[2 * j]     = ffma2(ik, make_float2(wv.x, wv.y), h[2 * j]);
            h[2 * j + 1] = ffma2(ik, make_float2(wv.z, wv.w), h[2 * j + 1]);
        }
    }
#pragma unroll
    for (int j = 0; j < HID / 2; j++) {
        h[j].x = fmaxf(h[j].x, 0.0f);
        h[j].y = fmaxf(h[j].y, 0.0f);
    }

    float2 o[ND / 2];
    {
        const float2* b2 = (const float2*)cO_b2;
#pragma unroll
        for (int t = 0; t < ND / 2; t++) o[t] = b2[t];
    }
    const float* hs = (const float*)h;
#pragma unroll
    for (int j = 0; j < HID; j++) {
        float2 hj = make_float2(hs[j], hs[j]);
        const float4* w = (const float4*)(cO_W2 + j * ND);
#pragma unroll
        for (int t = 0; t < ND / 4; t++) {
            float4 wv = w[t];
            o[2 * t]     = ffma2(hj, make_float2(wv.x, wv.y), o[2 * t]);
            o[2 * t + 1] = ffma2(hj, make_float2(wv.z, wv.w), o[2 * t + 1]);
        }
    }

    float4* xo = (float4*)(x_new_out + (size_t)n * ND);
    const float4* o4 = (const float4*)o;
#pragma unroll
    for (int i = 0; i < ND / 4; i++) xo[i] = o4[i];
}

// ---------------------------------------------------------------------------
// kernel_launch
// Inputs: 0:x 1:edge_index 2:e 3:fR_W1 4:fR_b1 5:fR_W2 6:fR_b2
//         7:fO_W1 8:fO_b1 9:fO_W2 10:fO_b2
// Output: [x_new (50000*16) | e_new (1600000*16)] float32
// ---------------------------------------------------------------------------
extern "C" void kernel_launch(void* const* d_in, const int* in_sizes, int n_in,
                              void* d_out, int out_size) {
    const float* x  = (const float*)d_in[0];
    const void*  ei = d_in[1];
    const float* e  = (const float*)d_in[2];

    float* x_new = (float*)d_out;
    float* e_new = (float*)d_out + (size_t)N_NODES * ND;

    // Symbol addresses for the constant bank (host-side query; capture-safe)
    void *pRW1c, *pRW2, *pRb2, *pOW1, *pOb1, *pOW2, *pOb2;
    cudaGetSymbolAddress(&pRW1c, cR_W1c);
    cudaGetSymbolAddress(&pRW2, cR_W2);
    cudaGetSymbolAddress(&pRb2, cR_b2);
    cudaGetSymbolAddress(&pOW1, cO_W1);
    cudaGetSymbolAddress(&pOb1, cO_b1);
    cudaGetSymbolAddress(&pOW2, cO_W2);
    cudaGetSymbolAddress(&pOb2, cO_b2);

    copy_weights_kernel<<<1, 512>>>(
        (float*)pRW1c, (const float*)d_in[3],
        (float*)pRW2, (const float*)d_in[5],
        (float*)pRb2, (const float*)d_in[6],
        (float*)pOW1, (const float*)d_in[7],
        (float*)pOb1, (const float*)d_in[8],
        (float*)pOW2, (const float*)d_in[9],
        (float*)pOb2, (const float*)d_in[10]);

    detect_idx_kernel<<<1, 1>>>(ei);
    pre_kernel<<<N_NODES, HID>>>(x, (const float*)d_in[3], (const float*)d_in[4]);
    slot_shift_kernel<<<1, 32>>>();   // keep edge_kernel in ncu capture slot
    edge_kernel<<<N_EDGES / EPB, EPB>>>(e, ei, e_new);
    node_kernel<<<(N_NODES + 127) / 128, 128>>>(x, x_new);
}